// round 1
// baseline (speedup 1.0000x reference)
#include <cuda_runtime.h>

// TorchSTFT collapses analytically to an elementwise scale:
//   STFT -> mag/phase -> resynth is exact (sre=re, sim=im),
//   Hermitian-extended inverse DFT of a real frame is exact identity,
//   so windowed[f,n] = x_pad[f*HOP+n] * win[n]^2 / norm and OLA at position p
//   only ever touches x_pad[p]:
//     out[b,t] = x[b,t] * ( sum_f win[(t+400) - 200 f]^2 ) * invnorm
//   Periodic-Hann COLA sum at 75% overlap == 1.5 exactly in the interior.

#define TIME      160000
#define BATCH     32
#define ROW_VEC   (TIME / 4)              // float4 per row = 40000

static __device__ __constant__ double kPI = 3.14159265358979323846;

// invnorm = sqrt(1 - hop_ratio + 1e-8) = sqrt(0.75000001)
#define INVNORM_D 0.8660254095579639
// interior gain = 1.5 * invnorm
#define CGAIN_F   1.2990381143369458f

// Exact partial COLA gain for boundary samples (valid for ALL t; used only
// where the 4-term sum may be clipped). Double cos for exactness; this path
// covers <0.3% of elements so its cost is invisible under the memory roofline.
__device__ __forceinline__ float edge_gain(int t) {
    int p = t + 400;                       // position in padded/OLA coordinates
    int a = p - 799;
    int fmin = (a > 0) ? (a + 199) / 200 : 0;   // ceil((p-799)/200), clamped at 0
    int fmax = p / 200;
    if (fmax > 800) fmax = 800;                 // F-1 = 800
    double s = 0.0;
    for (int f = fmin; f <= fmax; ++f) {
        int n = p - 200 * f;                    // 0 <= n < 800
        double w = 0.5 - 0.5 * cos(2.0 * kPI * (double)n / 800.0);
        s += w * w;
    }
    return (float)(s * INVNORM_D);
}

__global__ void __launch_bounds__(256)
torchstft_scale_kernel(const float4* __restrict__ in, float4* __restrict__ out) {
    int v = blockIdx.x * blockDim.x + threadIdx.x;   // 0 .. BATCH*ROW_VEC-1
    // t0 = element offset within the row (rows are float4-aligned: TIME%4==0)
    int row = v / ROW_VEC;
    int t0 = (v - row * ROW_VEC) * 4;

    float4 x = in[v];
    if (t0 >= 200 && t0 < 159796) {
        // interior: constant COLA gain
        x.x *= CGAIN_F;
        x.y *= CGAIN_F;
        x.z *= CGAIN_F;
        x.w *= CGAIN_F;
    } else {
        x.x *= edge_gain(t0);
        x.y *= edge_gain(t0 + 1);
        x.z *= edge_gain(t0 + 2);
        x.w *= edge_gain(t0 + 3);
    }
    out[v] = x;
}

extern "C" void kernel_launch(void* const* d_in, const int* in_sizes, int n_in,
                              void* d_out, int out_size) {
    (void)in_sizes; (void)n_in; (void)out_size;
    const float4* in = (const float4*)d_in[0];
    float4* out = (float4*)d_out;
    int total_vec = BATCH * ROW_VEC;                 // 1,280,000
    int threads = 256;
    int blocks = (total_vec + threads - 1) / threads; // 5000
    torchstft_scale_kernel<<<blocks, threads>>>(in, out);
}

// round 4
// speedup vs baseline: 1.6105x; 1.6105x over previous
#include <cuda_runtime.h>

// TorchSTFT collapses analytically to an elementwise scale (see R1):
//   out[b,t] = x[b,t] * COLA(t+400) * invnorm
// with COLA == 1.5 exactly for t in [200, 159800) (periodic Hann, 75% overlap),
// and an explicit partial sum on the ~400 edge samples per row.
//
// R2-R4: 4 float4 per thread, loads batched up front (4x MLP -> DRAM-bound);
// float-only edge math via cospif (no FP64, lower register pressure).

#define TIME      160000
#define BATCH     32
#define ROW_VEC   (TIME / 4)              // 40000 float4 per row
#define TOTAL_VEC (BATCH * ROW_VEC)       // 1,280,000
#define VPT       4                       // float4 vectors per thread
#define TPB       256

// invnorm = sqrt(1 - 0.25 + 1e-8)
#define INVNORM_F 0.86602540956f
// interior gain = 1.5 * invnorm
#define CGAIN_F   1.29903811433f

// Exact partial COLA gain (float). Valid for all t; used only on edge vectors.
__device__ __forceinline__ float edge_gain(int t) {
    int p = t + 400;                          // OLA-coordinate position
    int fmin = (p > 799) ? (p - 799 + 199) / 200 : 0;
    int fmax = p / 200;
    if (fmax > 800) fmax = 800;               // F-1 = 800
    float s = 0.0f;
    for (int f = fmin; f <= fmax; ++f) {
        int n = p - 200 * f;                  // 0..799
        // hann_periodic(n) = 0.5 - 0.5*cos(2*pi*n/800) = 0.5 - 0.5*cospi(n/400)
        float w = 0.5f - 0.5f * cospif((float)n * (1.0f / 400.0f));
        s += w * w;
    }
    return s * INVNORM_F;
}

__global__ void __launch_bounds__(TPB)
torchstft_scale_kernel(const float4* __restrict__ in, float4* __restrict__ out) {
    int base = blockIdx.x * (TPB * VPT) + threadIdx.x;

    // Batch all loads first: 4 independent LDG.128 in flight per thread.
    float4 v[VPT];
#pragma unroll
    for (int k = 0; k < VPT; ++k)
        v[k] = in[base + k * TPB];

#pragma unroll
    for (int k = 0; k < VPT; ++k) {
        int idx = base + k * TPB;
        int row = idx / ROW_VEC;
        int t0  = (idx - row * ROW_VEC) * 4;  // element offset within row
        if (t0 >= 200 && t0 <= 159796) {      // whole vector in COLA interior
            v[k].x *= CGAIN_F;
            v[k].y *= CGAIN_F;
            v[k].z *= CGAIN_F;
            v[k].w *= CGAIN_F;
        } else {
            v[k].x *= edge_gain(t0);
            v[k].y *= edge_gain(t0 + 1);
            v[k].z *= edge_gain(t0 + 2);
            v[k].w *= edge_gain(t0 + 3);
        }
        out[idx] = v[k];
    }
}

extern "C" void kernel_launch(void* const* d_in, const int* in_sizes, int n_in,
                              void* d_out, int out_size) {
    (void)in_sizes; (void)n_in; (void)out_size;
    const float4* in = (const float4*)d_in[0];
    float4* out = (float4*)d_out;
    int blocks = TOTAL_VEC / (TPB * VPT);     // 1250, exact
    torchstft_scale_kernel<<<blocks, TPB>>>(in, out);
}